// round 14
// baseline (speedup 1.0000x reference)
#include <cuda_runtime.h>

// ReactantCentreIdentify — fused segment-mean-gate-concat.
//   node_rep      [N=400000, D=300] f32
//   batch         [N] i32, SORTED ascending in [0, B=4096)
//   primary_label [N] i32 in {-1, 0}
//   out           [N, 600] f32 = [node_rep | cond_pool[batch]]
//
// Hybrid decomposition:
//   graphs [0, 3584): ONE full-width CTA per graph — the proven R7 engine
//     (block (75,6), 4 CTAs/SM = 60 warps, 76%+ DRAM steady state).
//   graphs [3584, 4096): TWO sync-free column-split CTAs per graph
//     (cols [0,38) / [38,75)) — these are the drain-tail CTAs; halving their
//     quantum halves the end-of-kernel occupancy-ramp window, and the
//     half-width efficiency tax lands where DRAM isn't saturated anyway.
// Pooled mean of a column subset needs only those columns + the count (from
// labels) => split CTAs are fully independent. Windowed binary search;
// L2 prefetch 12 rows ahead.

#define D4   75          // D/4 float4 per input row
#define OUT4 150         // 2D/4 float4 per output row
#define BY   6           // row lanes per block
#define PFR  12          // prefetch distance in rows
#define NGRAPH 4096
#define SPLITG 3584      // graphs >= SPLITG are handled by 2 column-half CTAs
#define SWIN 2048        // binary-search half-window (6.5 sigma; has fallback)

__global__ __launch_bounds__(D4 * BY, 4)
void reactant_centre_kernel(const float4* __restrict__ x4,     // [N, 75]
                            const int*    __restrict__ batch,  // [N]
                            const int*    __restrict__ label,  // [N]
                            float4*       __restrict__ out4,   // [N, 150]
                            int n)
{
    const int bid = blockIdx.x;
    const int c4  = threadIdx.x;   // 0..74  (float4 column)
    const int ry  = threadIdx.y;   // 0..BY-1 (row lane)
    const int tid = ry * D4 + c4;

    // bid -> (graph, column range)
    int g, c0, c1;
    if (bid < SPLITG) {
        g = bid; c0 = 0; c1 = D4;                  // full width
    } else {
        int i = bid - SPLITG;
        g  = SPLITG + (i >> 1);
        c0 = (i & 1) ? 38 : 0;                     // column half
        c1 = (i & 1) ? D4 : 38;
    }
    const bool act = (c4 >= c0) && (c4 < c1);

    __shared__ int    s_se[2];
    __shared__ float4 s_acc[BY][D4];
    __shared__ int    s_cnt[BY];
    __shared__ float4 s_pool[D4];

    // lower_bound for g and g+1, windowed around the expected position.
    if (tid < 2) {
        int target = g + tid;
        long est = ((long)target * n) / NGRAPH;
        int lo = (int)(est - SWIN); if (lo < 0) lo = 0;
        int hi = (int)(est + SWIN); if (hi > n) hi = n;
        // correctness fallback if the window assumption ever fails
        if (lo > 0 && batch[lo] >= target) lo = 0;
        if (hi < n && batch[hi - 1] < target) hi = n;
        while (lo < hi) {
            int mid = (lo + hi) >> 1;
            if (batch[mid] < target) lo = mid + 1; else hi = mid;
        }
        s_se[tid] = lo;
    }
    __syncthreads();
    const int s = s_se[0];
    const int e = s_se[1];

    const bool do_pf = act && (((c4 - c0) & 7) == 0);  // one prefetch per 128B
    const int  pmax  = n - 1;

    // ---- Pass 1: copy left half (my cols) + accumulate condition rows ----
    float4 acc = make_float4(0.f, 0.f, 0.f, 0.f);
    int cnt = 0;
    for (int r = s + ry; r < e; r += BY) {
        if (do_pf) {
            int rp = r + PFR;                 // may cross into next graph:
            if (rp > pmax) rp = pmax;         // harmless pre-warming
            asm volatile("prefetch.global.L2 [%0];"
                         :: "l"(x4 + (long)rp * D4 + c4));
        }
        if (act) {
            float4 v = x4[(long)r * D4 + c4];
            int   l = label[r];
            out4[(long)r * OUT4 + c4] = v;
            if (l == -1) {
                acc.x += v.x; acc.y += v.y; acc.z += v.z; acc.w += v.w;
                cnt++;
            }
        }
    }
    s_acc[ry][c4] = acc;
    if (c4 == c0) s_cnt[ry] = cnt;
    __syncthreads();

    // Gate: pool only if the LAST node of the graph is a condition node.
    const bool flag = (e > s) && (label[e - 1] == -1);

    if (ry == 0 && act) {
        float4 t = s_acc[0][c4];
        int tc_i = s_cnt[0];
        #pragma unroll
        for (int k = 1; k < BY; k++) {
            float4 a = s_acc[k][c4];
            t.x += a.x; t.y += a.y; t.z += a.z; t.w += a.w;
            tc_i += s_cnt[k];
        }
        float inv = flag ? (1.0f / fmaxf((float)tc_i, 1.0f)) : 0.0f;
        s_pool[c4] = make_float4(t.x * inv, t.y * inv, t.z * inv, t.w * inv);
    }
    __syncthreads();

    // ---- Pass 2: broadcast pooled vector into right half (my cols) ----
    const float4 p = s_pool[c4];
    for (int r = s + ry; r < e; r += BY) {
        if (act) out4[(long)r * OUT4 + D4 + c4] = p;
    }
}

extern "C" void kernel_launch(void* const* d_in, const int* in_sizes, int n_in,
                              void* d_out, int out_size)
{
    const float* node_rep = (const float*)d_in[0];
    const int*   batch    = (const int*)d_in[1];
    const int*   label    = (const int*)d_in[2];
    (void)n_in; (void)out_size;

    const int n = in_sizes[1];        // N from batch array

    const int grid = SPLITG + 2 * (NGRAPH - SPLITG);   // 3584 + 1024 = 4608
    dim3 block(D4, BY);               // 75 x 6 = 450 threads
    reactant_centre_kernel<<<grid, block>>>((const float4*)node_rep, batch,
                                            label, (float4*)d_out, n);
}